// round 2
// baseline (speedup 1.0000x reference)
#include <cuda_runtime.h>

#define T_STEPS 800
#define UNITS   1024
#define BATCH   32
#define NFEAT   161
#define GRID    128
#define TPB     256
#define CLIPV   20.0f

// rnn tiling: 128 CTAs = 2 dirs x 64 column tiles of 16 cols. No k-split.
#define COLS_CTA 16
#define CHUNK_K  128
#define NCHUNK   (UNITS / CHUNK_K)   // 8

// SMEM layout (dynamic): U splatted pairs + h double buffer + reduce scratch
#define SMEM_U_BYTES   (UNITS * COLS_CTA * 8)          // 131072
#define SMEM_H_BYTES   (2 * CHUNK_K * BATCH * 4)       // 32768
#define SMEM_RED_ULL   (COLS_CTA * 16 * 9)             // 2304 ull (pad 9 kills conflicts)
#define SMEM_BYTES     (SMEM_U_BYTES + SMEM_H_BYTES + SMEM_RED_ULL * 8)

__device__ float    g_xw[T_STEPS * UNITS * BATCH];   // [t][u][b]
__device__ float    g_h[2 * 2 * UNITS * BATCH];      // [buf][dir][u][b]
__device__ unsigned g_bar;

typedef unsigned long long ull;

__device__ __forceinline__ void fma2(ull& d, ull a, ull b) {
    asm("fma.rn.f32x2 %0, %1, %2, %0;" : "+l"(d) : "l"(a), "l"(b));
}
__device__ __forceinline__ ull pack2(float v) {
    ull r; asm("mov.b64 %0, {%1, %1};" : "=l"(r) : "f"(v)); return r;
}
__device__ __forceinline__ float2 unpack2(ull v) {
    float2 r; asm("mov.b64 {%0, %1}, %2;" : "=f"(r.x), "=f"(r.y) : "l"(v)); return r;
}

// ---------------------------------------------------------------------------
__global__ void init_kernel() {
    int i = blockIdx.x * blockDim.x + threadIdx.x;
    if (i < 2 * UNITS * BATCH) g_h[i] = 0.0f;   // zero buf0, both dirs
    if (i == 0) g_bar = 0u;
}

// ---------------------------------------------------------------------------
// xw[t][u][b] = sum_f inputs[b][t][f] * W[f][u] + bias[u]   (unchanged, passed R1)
// ---------------------------------------------------------------------------
__global__ void __launch_bounds__(TPB) xw_kernel(const float* __restrict__ inp,
                                                 const float* __restrict__ W,
                                                 const float* __restrict__ bias) {
    __shared__ __align__(16) float in_s[NFEAT * 36];
    const int t   = blockIdx.y;
    const int u0  = blockIdx.x * 128;
    const int tid = threadIdx.x;
    const int bq  = tid & 7;
    const int cq  = tid >> 3;

    for (int idx = tid; idx < BATCH * NFEAT; idx += TPB) {
        int b = idx / NFEAT;
        int f = idx - b * NFEAT;
        in_s[f * 36 + b] = inp[(b * T_STEPS + t) * NFEAT + f];
    }
    __syncthreads();

    ull acc[4][2];
    #pragma unroll
    for (int i = 0; i < 4; i++) { acc[i][0] = 0ull; acc[i][1] = 0ull; }

    const float4* Wp = reinterpret_cast<const float4*>(W) + (u0 >> 2) + cq;
    #pragma unroll 1
    for (int f = 0; f < NFEAT; f++) {
        ulonglong2 ip = *reinterpret_cast<const ulonglong2*>(&in_s[f * 36 + bq * 4]);
        float4 w4 = __ldg(Wp + f * (UNITS / 4));
        ull w0 = pack2(w4.x), w1 = pack2(w4.y), w2 = pack2(w4.z), w3 = pack2(w4.w);
        fma2(acc[0][0], ip.x, w0); fma2(acc[0][1], ip.y, w0);
        fma2(acc[1][0], ip.x, w1); fma2(acc[1][1], ip.y, w1);
        fma2(acc[2][0], ip.x, w2); fma2(acc[2][1], ip.y, w2);
        fma2(acc[3][0], ip.x, w3); fma2(acc[3][1], ip.y, w3);
    }
    #pragma unroll
    for (int i = 0; i < 4; i++) {
        int u = u0 + cq * 4 + i;
        float bu = __ldg(bias + u);
        float2 a0 = unpack2(acc[i][0]);
        float2 a1 = unpack2(acc[i][1]);
        float4 v = make_float4(a0.x + bu, a0.y + bu, a1.x + bu, a1.y + bu);
        *reinterpret_cast<float4*>(&g_xw[(t * UNITS + u) * BATCH + bq * 4]) = v;
    }
}

// ---------------------------------------------------------------------------
__device__ __forceinline__ void grid_sync(unsigned target) {
    __syncthreads();
    if (threadIdx.x == 0) {
        unsigned* bar = &g_bar;
        asm volatile("red.release.gpu.global.add.u32 [%0], %1;"
                     :: "l"(bar), "r"(1u) : "memory");
        unsigned v;
        do {
            asm volatile("ld.acquire.gpu.global.u32 %0, [%1];"
                         : "=r"(v) : "l"(bar) : "memory");
        } while (v < target);
    }
    __syncthreads();
}

// ---------------------------------------------------------------------------
// Persistent bidirectional scan. CTA = (dir, 16 cols). Full k in-CTA:
// one grid barrier per timestep, no cross-SM partial reduction.
// ---------------------------------------------------------------------------
__global__ void __launch_bounds__(TPB, 1) rnn_kernel(const float* __restrict__ Uw,
                                                     float* __restrict__ out) {
    extern __shared__ __align__(16) char smem_raw[];
    ull*   U_dup = reinterpret_cast<ull*>(smem_raw);                       // [1024][16] splat pairs
    float* h_s   = reinterpret_cast<float*>(smem_raw + SMEM_U_BYTES);      // [2][128][32]
    ull*   red_s = reinterpret_cast<ull*>(smem_raw + SMEM_U_BYTES + SMEM_H_BYTES);

    const int tid = threadIdx.x;
    const int bid = blockIdx.x;
    const int dir = bid >> 6;            // 0 fwd, 1 bwd
    const int c0  = (bid & 63) * COLS_CTA;

    const int cg = tid & 3;              // 4 col groups of 4
    const int bg = (tid >> 2) & 7;       // 8 batch groups of 4
    const int ks = tid >> 5;             // warp-id = k-slice (k ≡ ks mod 8)

    // epilogue identity: one f32x2 output per thread
    const int o_col = tid >> 4;          // 0..15
    const int o_bp  = tid & 15;          // 0..15 (b = 2*o_bp)
    const int go_col = c0 + o_col;
    const int go_b   = o_bp * 2;

    // ---- build splatted U slice once (128 KB) ----
    for (int idx = tid; idx < UNITS * COLS_CTA / 4; idx += TPB) {
        int k = idx >> 2, cq = idx & 3;
        float4 v = __ldg(reinterpret_cast<const float4*>(Uw + k * UNITS + c0) + cq);
        ull* dst = U_dup + k * COLS_CTA + cq * 4;
        dst[0] = pack2(v.x); dst[1] = pack2(v.y);
        dst[2] = pack2(v.z); dst[3] = pack2(v.w);
    }

    int p = 0;
    unsigned bseq = 0;

    for (int t = 0; t < T_STEPS; t++) {
        const float* hrd = g_h + (p * 2 + dir) * (UNITS * BATCH);

        // prefetch x_t (consumed ~4000 cyc later)
        int tx = dir ? (T_STEPS - 1 - t) : t;
        float2 xv = __ldcs(reinterpret_cast<const float2*>(
                        g_xw + (tx * UNITS + go_col) * BATCH + go_b));

        // prefetch chunk 0
        float4 pf[4];
        {
            const float4* src = reinterpret_cast<const float4*>(hrd);
            #pragma unroll
            for (int j = 0; j < 4; j++) pf[j] = __ldcg(src + tid + j * TPB);
        }

        ull acc[4][2];
        #pragma unroll
        for (int j = 0; j < 4; j++) { acc[j][0] = 0ull; acc[j][1] = 0ull; }

        #pragma unroll 1
        for (int c = 0; c < NCHUNK; c++) {
            float* buf = h_s + (c & 1) * (CHUNK_K * BATCH);
            #pragma unroll
            for (int j = 0; j < 4; j++)
                reinterpret_cast<float4*>(buf)[tid + j * TPB] = pf[j];
            __syncthreads();
            if (c + 1 < NCHUNK) {
                const float4* src = reinterpret_cast<const float4*>(hrd)
                                    + (c + 1) * (CHUNK_K * BATCH / 4);
                #pragma unroll
                for (int j = 0; j < 4; j++) pf[j] = __ldcg(src + tid + j * TPB);
            }
            // compute: k_local = i*8 + ks, 16 iters
            const float* hp0 = buf + ks * BATCH + bg * 4;
            const ull*   up0 = U_dup + (c * CHUNK_K + ks) * COLS_CTA + cg * 4;
            #pragma unroll
            for (int i = 0; i < 16; i++) {
                ulonglong2 hp = *reinterpret_cast<const ulonglong2*>(hp0 + i * 8 * BATCH);
                ulonglong2 ua = *reinterpret_cast<const ulonglong2*>(up0 + i * 8 * COLS_CTA);
                ulonglong2 ub = *reinterpret_cast<const ulonglong2*>(up0 + i * 8 * COLS_CTA + 2);
                fma2(acc[0][0], hp.x, ua.x); fma2(acc[0][1], hp.y, ua.x);
                fma2(acc[1][0], hp.x, ua.y); fma2(acc[1][1], hp.y, ua.y);
                fma2(acc[2][0], hp.x, ub.x); fma2(acc[2][1], hp.y, ub.x);
                fma2(acc[3][0], hp.x, ub.y); fma2(acc[3][1], hp.y, ub.y);
            }
        }

        // ---- intra-CTA 8-way k-slice reduction ----
        #pragma unroll
        for (int j = 0; j < 4; j++)
            #pragma unroll
            for (int i = 0; i < 2; i++)
                red_s[((cg * 4 + j) * 16 + (bg * 2 + i)) * 9 + ks] = acc[j][i];
        __syncthreads();

        {
            const ull* rp = red_s + (o_col * 16 + o_bp) * 9;
            float2 s = unpack2(rp[0]);
            #pragma unroll
            for (int r = 1; r < 8; r++) {
                float2 v = unpack2(rp[r]);
                s.x += v.x; s.y += v.y;
            }
            float2 hn;
            hn.x = fminf(fmaxf(xv.x + s.x, 0.f), CLIPV);
            hn.y = fminf(fmaxf(xv.y + s.y, 0.f), CLIPV);
            __stcg(reinterpret_cast<float2*>(
                       g_h + ((p ^ 1) * 2 + dir) * (UNITS * BATCH) + go_col * BATCH + go_b),
                   hn);
        }

        bseq++; grid_sync(bseq * GRID);
        p ^= 1;
    }

    // epilogue: out[b][u] = hf[u][b] + hb[u][b]  (final state in buf 0)
    {
        int o = bid * TPB + tid;
        int b = o >> 10;
        int u = o & 1023;
        float v = __ldcg(&g_h[u * BATCH + b]) +
                  __ldcg(&g_h[UNITS * BATCH + u * BATCH + b]);
        out[o] = v;
    }
}

// ---------------------------------------------------------------------------
extern "C" void kernel_launch(void* const* d_in, const int* in_sizes, int n_in,
                              void* d_out, int out_size) {
    const float* inp  = (const float*)d_in[0];  // [32, 800, 161]
    const float* W    = (const float*)d_in[1];  // [161, 1024]
    const float* Uw   = (const float*)d_in[2];  // [1024, 1024]
    const float* bias = (const float*)d_in[3];  // [1024]
    float* out        = (float*)d_out;          // [32, 1024]

    cudaFuncSetAttribute(rnn_kernel, cudaFuncAttributeMaxDynamicSharedMemorySize,
                         SMEM_BYTES);

    init_kernel<<<(2 * UNITS * BATCH + TPB - 1) / TPB, TPB>>>();
    xw_kernel<<<dim3(8, T_STEPS, 1), TPB>>>(inp, W, bias);
    rnn_kernel<<<GRID, TPB, SMEM_BYTES>>>(Uw, out);
}